// round 1
// baseline (speedup 1.0000x reference)
#include <cuda_runtime.h>
#include <cuda_bf16.h>
#include <cstdint>

// ---------------- problem constants ----------------
#define NN     8192
#define INF    128
#define HID    512
#define OUTF   256
#define H3     (3*HID)     // 1536
#define O3     (3*OUTF)    // 768

// ---------------- GEMM tiling ----------------
#define BM 128
#define BN 128
#define BK 32
#define ASTR (BK + 8)      // 40 bf16 per A smem row (pad)
#define BSTR (BN + 8)      // 136 bf16 per B smem row (pad)
#define AS_SIZE (BM * ASTR)   // 5120
#define BS_SIZE (BK * BSTR)   // 4352
#define SMEM_ELEMS (4*AS_SIZE + 4*BS_SIZE)   // hi/lo x double-buffer
#define SMEM_BYTES (SMEM_ELEMS * 2)          // 75776

// ---------------- device scratch (no allocs allowed) ----------------
__device__ float g_h [NN * H3];      // layer1 concat output  [8192,1536]
__device__ float g_ZT[NN * 1024];    // layer1 hop1/2 pre-prop
__device__ float g_U1[NN * 512];     // layer1 hop2 intermediate
__device__ float g_g [NN * O3];      // layer2 concat output  [8192,768]
__device__ float g_Z2[NN * 512];     // layer2 hop1/2 pre-prop
__device__ float g_U2[NN * 256];     // layer2 hop2 intermediate
__device__ float g_sc[H3];
__device__ float g_sh[H3];

// ---------------- helpers ----------------
__device__ __forceinline__ void ldsm_x4(uint32_t* r, uint32_t addr) {
    asm volatile("ldmatrix.sync.aligned.m8n8.x4.shared.b16 {%0,%1,%2,%3}, [%4];"
                 : "=r"(r[0]), "=r"(r[1]), "=r"(r[2]), "=r"(r[3]) : "r"(addr));
}
__device__ __forceinline__ void ldsm_x4_t(uint32_t* r, uint32_t addr) {
    asm volatile("ldmatrix.sync.aligned.m8n8.x4.trans.shared.b16 {%0,%1,%2,%3}, [%4];"
                 : "=r"(r[0]), "=r"(r[1]), "=r"(r[2]), "=r"(r[3]) : "r"(addr));
}
__device__ __forceinline__ void mma16816(float* c, const uint32_t* a, const uint32_t* b) {
    asm volatile("mma.sync.aligned.m16n8k16.row.col.f32.bf16.bf16.f32 "
                 "{%0,%1,%2,%3}, {%4,%5,%6,%7}, {%8,%9}, {%0,%1,%2,%3};"
                 : "+f"(c[0]), "+f"(c[1]), "+f"(c[2]), "+f"(c[3])
                 : "r"(a[0]), "r"(a[1]), "r"(a[2]), "r"(a[3]), "r"(b[0]), "r"(b[1]));
}

// fp32x4 -> (hi,lo) bf16x4 split, stored as 8B each
__device__ __forceinline__ void split_store4(float4 v, __nv_bfloat16* hp, __nv_bfloat16* lp) {
    __nv_bfloat162 h01 = __floats2bfloat162_rn(v.x, v.y);
    __nv_bfloat162 h23 = __floats2bfloat162_rn(v.z, v.w);
    float2 f01 = __bfloat1622float2(h01);
    float2 f23 = __bfloat1622float2(h23);
    __nv_bfloat162 l01 = __floats2bfloat162_rn(v.x - f01.x, v.y - f01.y);
    __nv_bfloat162 l23 = __floats2bfloat162_rn(v.z - f23.x, v.w - f23.y);
    uint2 hu, lu;
    hu.x = *reinterpret_cast<unsigned int*>(&h01);
    hu.y = *reinterpret_cast<unsigned int*>(&h23);
    lu.x = *reinterpret_cast<unsigned int*>(&l01);
    lu.y = *reinterpret_cast<unsigned int*>(&l23);
    *reinterpret_cast<uint2*>(hp) = hu;
    *reinterpret_cast<uint2*>(lp) = lu;
}

// ---------------- split-bf16 (fp32-accurate) GEMM ----------------
// C[M,N] = A[M,K] @ B[K,N] (+bias), A row-major lda, B row-major ldb.
// B may be "segmented": column c lives at B + (c/seg)*segstride + k*ldb + (c%seg).
// Epilogue: columns [0,split) -> out0 (ld0), columns [split,N) -> out1 (ld1).
// Requires: M%128==0, N%128==0, K%32==0, seg%128==0.
__global__ __launch_bounds__(256, 1) void gemm_splitbf16(
    const float* __restrict__ A, int lda,
    const float* __restrict__ B, int ldb, int seg, long segstride,
    const float* __restrict__ bias,
    float* __restrict__ out0, int ld0, int split,
    float* __restrict__ out1, int ld1,
    int K)
{
    extern __shared__ __nv_bfloat16 smem[];
    __nv_bfloat16* As_h = smem;
    __nv_bfloat16* As_l = As_h + 2 * AS_SIZE;
    __nv_bfloat16* Bs_h = As_l + 2 * AS_SIZE;
    __nv_bfloat16* Bs_l = Bs_h + 2 * BS_SIZE;

    const int tid  = threadIdx.x;
    const int lane = tid & 31;
    const int warp = tid >> 5;
    const int wm   = warp >> 2;   // 0..1 : 64-row slab
    const int wn   = warp & 3;    // 0..3 : 32-col slab

    const int m0 = blockIdx.y * BM;
    const int n0 = blockIdx.x * BN;

    const int jseg = n0 / seg;
    const float* Bb = B + (long)jseg * segstride + (n0 - jseg * seg);

    // staging: A tile 128x32 (4 passes of 32 rows), B tile 32x128 (4 passes of 8 rows)
    const int ar = tid >> 3;            // 0..31
    const int ac = (tid & 7) << 2;      // 0,4,...,28
    const int br = tid >> 5;            // 0..7
    const int bc = (tid & 31) << 2;     // 0,4,...,124

    const float* Aptr = A + (long)(m0 + ar) * lda + ac;
    const float* Bptr = Bb + (long)br * ldb + bc;

    float4 pa[4], pb[4];

#define LOAD_TILES(k0) do {                                                        \
    _Pragma("unroll") for (int p = 0; p < 4; p++)                                   \
        pa[p] = *(const float4*)(Aptr + (long)(32 * p) * lda + (k0));               \
    _Pragma("unroll") for (int p = 0; p < 4; p++)                                   \
        pb[p] = *(const float4*)(Bptr + (long)((k0) + 8 * p) * ldb);                \
} while (0)

#define STORE_TILES(bf_) do {                                                      \
    _Pragma("unroll") for (int p = 0; p < 4; p++) {                                 \
        int idx = (bf_) * AS_SIZE + (ar + 32 * p) * ASTR + ac;                      \
        split_store4(pa[p], As_h + idx, As_l + idx);                                \
    }                                                                               \
    _Pragma("unroll") for (int p = 0; p < 4; p++) {                                 \
        int idx = (bf_) * BS_SIZE + (br + 8 * p) * BSTR + bc;                       \
        split_store4(pb[p], Bs_h + idx, Bs_l + idx);                                \
    }                                                                               \
} while (0)

    float acc[4][4][4];
#pragma unroll
    for (int i = 0; i < 4; i++)
#pragma unroll
        for (int j = 0; j < 4; j++)
#pragma unroll
            for (int k = 0; k < 4; k++) acc[i][j][k] = 0.f;

    LOAD_TILES(0);
    STORE_TILES(0);
    __syncthreads();

    const int KT = K >> 5;
    int buf = 0;
    for (int kt = 0; kt < KT; kt++) {
        const bool has_next = (kt + 1 < KT);
        if (has_next) LOAD_TILES((kt + 1) << 5);   // LDGs overlap with MMAs below

#pragma unroll
        for (int ks = 0; ks < 2; ks++) {
            uint32_t ah[4][4], al[4][4], bh[4][2], bl[4][2];
            const int arow = wm * 64 + (lane & 15);
            const int acol = ks * 16 + ((lane >> 4) << 3);
#pragma unroll
            for (int mt = 0; mt < 4; mt++) {
                int idx = buf * AS_SIZE + (arow + mt * 16) * ASTR + acol;
                ldsm_x4(ah[mt], (uint32_t)__cvta_generic_to_shared(As_h + idx));
                ldsm_x4(al[mt], (uint32_t)__cvta_generic_to_shared(As_l + idx));
            }
            const int brow  = ks * 16 + (lane & 15);
            const int bcolb = wn * 32 + ((lane >> 4) << 3);
#pragma unroll
            for (int nt2 = 0; nt2 < 2; nt2++) {
                int idx = buf * BS_SIZE + brow * BSTR + bcolb + nt2 * 16;
                uint32_t r[4];
                ldsm_x4_t(r, (uint32_t)__cvta_generic_to_shared(Bs_h + idx));
                bh[nt2 * 2][0] = r[0]; bh[nt2 * 2][1] = r[1];
                bh[nt2 * 2 + 1][0] = r[2]; bh[nt2 * 2 + 1][1] = r[3];
                ldsm_x4_t(r, (uint32_t)__cvta_generic_to_shared(Bs_l + idx));
                bl[nt2 * 2][0] = r[0]; bl[nt2 * 2][1] = r[1];
                bl[nt2 * 2 + 1][0] = r[2]; bl[nt2 * 2 + 1][1] = r[3];
            }
#pragma unroll
            for (int mt = 0; mt < 4; mt++)
#pragma unroll
                for (int nt = 0; nt < 4; nt++) {
                    mma16816(acc[mt][nt], ah[mt], bh[nt]);   // hi*hi
                    mma16816(acc[mt][nt], ah[mt], bl[nt]);   // hi*lo
                    mma16816(acc[mt][nt], al[mt], bh[nt]);   // lo*hi
                }
        }
        __syncthreads();
        if (has_next) {
            buf ^= 1;
            STORE_TILES(buf);
            __syncthreads();
        }
    }

    // ---- epilogue: optional bias, split-destination store ----
#pragma unroll
    for (int mt = 0; mt < 4; mt++) {
        const int r0 = m0 + wm * 64 + mt * 16 + (lane >> 2);
#pragma unroll
        for (int nt = 0; nt < 4; nt++) {
            const int gc = n0 + wn * 32 + nt * 8 + ((lane & 3) << 1);
            float2 v0 = make_float2(acc[mt][nt][0], acc[mt][nt][1]);
            float2 v1 = make_float2(acc[mt][nt][2], acc[mt][nt][3]);
            if (bias) {
                float b0 = bias[gc], b1v = bias[gc + 1];
                v0.x += b0; v0.y += b1v; v1.x += b0; v1.y += b1v;
            }
            float *p0, *p1;
            if (gc < split) {
                p0 = out0 + (long)r0 * ld0 + gc;
                p1 = out0 + (long)(r0 + 8) * ld0 + gc;
            } else {
                p0 = out1 + (long)r0 * ld1 + (gc - split);
                p1 = out1 + (long)(r0 + 8) * ld1 + (gc - split);
            }
            *reinterpret_cast<float2*>(p0) = v0;
            *reinterpret_cast<float2*>(p1) = v1;
        }
    }
#undef LOAD_TILES
#undef STORE_TILES
}

// ---------------- batchnorm (training-mode stats) ----------------
// 48 blocks x 256 threads; block handles 32 columns, 8 row-groups per column.
__global__ void bn_stats(const float* __restrict__ h,
                         const float* __restrict__ gamma,
                         const float* __restrict__ beta,
                         float* __restrict__ sc, float* __restrict__ sh)
{
    __shared__ float ss[8][32], sq[8][32];
    const int c   = threadIdx.x & 31;
    const int col = blockIdx.x * 32 + c;
    const int rg  = threadIdx.x >> 5;
    float s = 0.f, s2 = 0.f;
    for (int r = rg; r < NN; r += 8) {
        float v = h[(long)r * H3 + col];
        s += v; s2 += v * v;
    }
    ss[rg][c] = s; sq[rg][c] = s2;
    __syncthreads();
    if (rg == 0) {
#pragma unroll
        for (int k = 1; k < 8; k++) { s += ss[k][c]; s2 += sq[k][c]; }
        const float mean = s * (1.f / NN);
        const float var  = s2 * (1.f / NN) - mean * mean;
        const float scale = gamma[col] * rsqrtf(var + 1e-5f);
        sc[col] = scale;
        sh[col] = beta[col] - mean * scale;
    }
}

// h = relu(h*sc + sh), vectorized float4 (H3 % 4 == 0)
__global__ void bn_apply_relu(float* __restrict__ h,
                              const float* __restrict__ sc,
                              const float* __restrict__ sh)
{
    const long i = ((long)blockIdx.x * blockDim.x + threadIdx.x) * 4;
    float4 v = *reinterpret_cast<float4*>(h + i);
    const int c = (int)(i % H3);
    v.x = fmaxf(0.f, v.x * sc[c]     + sh[c]);
    v.y = fmaxf(0.f, v.y * sc[c + 1] + sh[c + 1]);
    v.z = fmaxf(0.f, v.z * sc[c + 2] + sh[c + 2]);
    v.w = fmaxf(0.f, v.w * sc[c + 3] + sh[c + 3]);
    *reinterpret_cast<float4*>(h + i) = v;
}

// ---------------- launcher ----------------
static inline void run_gemm(const float* A, int lda,
                            const float* B, int ldb, int seg, long segstride,
                            const float* bias,
                            float* o0, int ld0, int split, float* o1, int ld1,
                            int M, int N, int K)
{
    dim3 grid(N / BN, M / BM);
    gemm_splitbf16<<<grid, 256, SMEM_BYTES>>>(A, lda, B, ldb, seg, segstride,
                                              bias, o0, ld0, split, o1, ld1, K);
}

extern "C" void kernel_launch(void* const* d_in, const int* in_sizes, int n_in,
                              void* d_out, int out_size)
{
    const float* x     = (const float*)d_in[0];   // [8192,128]
    const float* adj   = (const float*)d_in[1];   // [8192,8192]
    const float* W1    = (const float*)d_in[2];   // [3,128,512]
    const float* b1    = (const float*)d_in[3];   // [3,512] -> flat 1536
    const float* W2    = (const float*)d_in[4];   // [3,1536,256]
    const float* b2    = (const float*)d_in[5];   // [3,256] -> flat 768
    const float* gamma = (const float*)d_in[6];   // [1536]
    const float* beta  = (const float*)d_in[7];   // [1536]
    const float* Wf    = (const float*)d_in[8];   // [768,256]
    const float* bf    = (const float*)d_in[9];   // [256]
    float* out = (float*)d_out;                   // [8192,256]

    float *h, *ZT, *U1, *g, *Z2, *U2, *sc, *sh;
    cudaGetSymbolAddress((void**)&h,  g_h);
    cudaGetSymbolAddress((void**)&ZT, g_ZT);
    cudaGetSymbolAddress((void**)&U1, g_U1);
    cudaGetSymbolAddress((void**)&g,  g_g);
    cudaGetSymbolAddress((void**)&Z2, g_Z2);
    cudaGetSymbolAddress((void**)&U2, g_U2);
    cudaGetSymbolAddress((void**)&sc, g_sc);
    cudaGetSymbolAddress((void**)&sh, g_sh);

    cudaFuncSetAttribute(gemm_splitbf16,
                         cudaFuncAttributeMaxDynamicSharedMemorySize, SMEM_BYTES);

    // ---- layer 1 ----
    // G1: x @ [W1_0|W1_1|W1_2] + b1  -> hop0 into h[:,0:512], hops1/2 into ZT
    run_gemm(x, INF, W1, HID, HID, (long)INF * HID, b1,
             h, H3, HID, ZT, 1024, NN, H3, INF);
    // G2: adj @ ZT -> hop1 into h[:,512:1024], hop2-intermediate into U1
    run_gemm(adj, NN, ZT, 1024, 1024, 0, nullptr,
             h + HID, H3, HID, U1, HID, NN, 1024, NN);
    // G3: adj @ U1 -> hop2 into h[:,1024:1536]
    run_gemm(adj, NN, U1, HID, HID, 0, nullptr,
             h + 2 * HID, H3, HID, nullptr, 0, NN, HID, NN);

    // ---- batchnorm + relu ----
    bn_stats<<<H3 / 32, 256>>>(h, gamma, beta, sc, sh);
    bn_apply_relu<<<(NN * H3 / 4) / 256, 256>>>(h, sc, sh);

    // ---- layer 2 ----
    // G4: h @ [W2_0|W2_1|W2_2] + b2 -> hop0 into g[:,0:256], hops1/2 into Z2
    run_gemm(h, H3, W2, OUTF, OUTF, (long)H3 * OUTF, b2,
             g, O3, OUTF, Z2, 2 * OUTF, NN, O3, H3);
    // G5: adj @ Z2 -> hop1 into g[:,256:512], hop2-intermediate into U2
    run_gemm(adj, NN, Z2, 2 * OUTF, 2 * OUTF, 0, nullptr,
             g + OUTF, O3, OUTF, U2, OUTF, NN, 2 * OUTF, NN);
    // G6: adj @ U2 -> hop2 into g[:,512:768]
    run_gemm(adj, NN, U2, OUTF, OUTF, 0, nullptr,
             g + 2 * OUTF, O3, OUTF, nullptr, 0, NN, OUTF, NN);

    // ---- final linear ----
    run_gemm(g, O3, Wf, OUTF, OUTF, 0, bf,
             out, OUTF, OUTF, nullptr, 0, NN, OUTF, O3);
}

// round 3
// speedup vs baseline: 1.0831x; 1.0831x over previous
#include <cuda_runtime.h>
#include <cuda_bf16.h>
#include <cstdint>

// ---------------- problem constants ----------------
#define NN     8192
#define INF    128
#define HID    512
#define OUTF   256
#define H3     (3*HID)     // 1536
#define O3     (3*OUTF)    // 768

// ---------------- GEMM tiling ----------------
#define BM 128
#define BN 128
#define BK 32
#define ST 4               // pipeline stages
#define ASTR (BK + 8)      // 40 bf16 per A smem row (80B, 16B-multiple)
#define BSTR (BN + 8)      // 136 bf16 per B smem row (272B, 16B-multiple)
#define AS_SIZE (BM * ASTR)   // 5120 elems
#define BS_SIZE (BK * BSTR)   // 4352 elems
#define SMEM_ELEMS (ST * 2 * (AS_SIZE + BS_SIZE))   // 75776
#define SMEM_BYTES (SMEM_ELEMS * 2)                 // 151552

// ---------------- device scratch: everything pre-split into bf16 hi/lo ----------------
__device__ __nv_bfloat16 g_adj_h[(long)NN * NN], g_adj_l[(long)NN * NN];
__device__ __nv_bfloat16 g_x_h [NN * INF],      g_x_l [NN * INF];
__device__ __nv_bfloat16 g_w1_h[3 * INF * HID], g_w1_l[3 * INF * HID];
__device__ __nv_bfloat16 g_w2_h[3 * H3 * OUTF], g_w2_l[3 * H3 * OUTF];
__device__ __nv_bfloat16 g_wf_h[O3 * OUTF],     g_wf_l[O3 * OUTF];
__device__ __nv_bfloat16 g_hh  [NN * H3],       g_hl  [NN * H3];
__device__ __nv_bfloat16 g_zth [NN * 1024],     g_ztl [NN * 1024];
__device__ __nv_bfloat16 g_u1h [NN * HID],      g_u1l [NN * HID];
__device__ __nv_bfloat16 g_gh  [NN * O3],       g_gl  [NN * O3];
__device__ __nv_bfloat16 g_z2h [NN * 512],      g_z2l [NN * 512];
__device__ __nv_bfloat16 g_u2h [NN * OUTF],     g_u2l [NN * OUTF];
__device__ float g_sc[H3], g_sh[H3];

// ---------------- helpers ----------------
__device__ __forceinline__ void ldsm_x4(uint32_t* r, uint32_t addr) {
    asm volatile("ldmatrix.sync.aligned.m8n8.x4.shared.b16 {%0,%1,%2,%3}, [%4];"
                 : "=r"(r[0]), "=r"(r[1]), "=r"(r[2]), "=r"(r[3]) : "r"(addr));
}
__device__ __forceinline__ void ldsm_x4_t(uint32_t* r, uint32_t addr) {
    asm volatile("ldmatrix.sync.aligned.m8n8.x4.trans.shared.b16 {%0,%1,%2,%3}, [%4];"
                 : "=r"(r[0]), "=r"(r[1]), "=r"(r[2]), "=r"(r[3]) : "r"(addr));
}
__device__ __forceinline__ void mma16816(float* c, const uint32_t* a, const uint32_t* b) {
    asm volatile("mma.sync.aligned.m16n8k16.row.col.f32.bf16.bf16.f32 "
                 "{%0,%1,%2,%3}, {%4,%5,%6,%7}, {%8,%9}, {%0,%1,%2,%3};"
                 : "+f"(c[0]), "+f"(c[1]), "+f"(c[2]), "+f"(c[3])
                 : "r"(a[0]), "r"(a[1]), "r"(a[2]), "r"(a[3]), "r"(b[0]), "r"(b[1]));
}
__device__ __forceinline__ void cpasync16(uint32_t dst, const void* src) {
    asm volatile("cp.async.cg.shared.global [%0], [%1], 16;" :: "r"(dst), "l"(src));
}
__device__ __forceinline__ void cp_commit() { asm volatile("cp.async.commit_group;"); }
__device__ __forceinline__ void cp_wait2()  { asm volatile("cp.async.wait_group 2;"); }

// (a,b) fp32 -> hi/lo bf16x2 packed as uint32
__device__ __forceinline__ void split2(float a, float b, uint32_t& hi, uint32_t& lo) {
    __nv_bfloat162 h = __floats2bfloat162_rn(a, b);
    float2 f = __bfloat1622float2(h);
    __nv_bfloat162 l = __floats2bfloat162_rn(a - f.x, b - f.y);
    hi = *reinterpret_cast<uint32_t*>(&h);
    lo = *reinterpret_cast<uint32_t*>(&l);
}

// ---------------- fp32 -> split bf16 conversion (4 elems/thread) ----------------
__global__ void convert_split(const float* __restrict__ in,
                              __nv_bfloat16* __restrict__ oh,
                              __nv_bfloat16* __restrict__ ol, long n)
{
    long i = ((long)blockIdx.x * blockDim.x + threadIdx.x) * 4;
    if (i >= n) return;
    float4 v = *reinterpret_cast<const float4*>(in + i);
    uint32_t h0, l0, h1, l1;
    split2(v.x, v.y, h0, l0);
    split2(v.z, v.w, h1, l1);
    *reinterpret_cast<uint2*>(oh + i) = make_uint2(h0, h1);
    *reinterpret_cast<uint2*>(ol + i) = make_uint2(l0, l1);
}

// ---------------- split-bf16 (fp32-accurate) GEMM, cp.async 4-stage pipeline ----------
// C[M,N] = (Ah+Al)[M,K] @ (Bh+Bl)[K,N] (+bias). Row-major, element strides.
// B segmented: col c at B + (c/seg)*segstride + k*ldb + (c%seg).
// Epilogue: if outF -> fp32 row-major; else split bf16, cols [0,split)->o0, rest->o1.
__global__ __launch_bounds__(256, 1) void gemm_bf16split(
    const __nv_bfloat16* __restrict__ Ah, const __nv_bfloat16* __restrict__ Al, int lda,
    const __nv_bfloat16* __restrict__ Bh, const __nv_bfloat16* __restrict__ Bl,
    int ldb, int seg, long segstride,
    const float* __restrict__ bias,
    __nv_bfloat16* __restrict__ o0h, __nv_bfloat16* __restrict__ o0l, int ld0, int split,
    __nv_bfloat16* __restrict__ o1h, __nv_bfloat16* __restrict__ o1l, int ld1,
    float* __restrict__ outF, int ldF,
    int K)
{
    extern __shared__ __nv_bfloat16 smem[];
    __nv_bfloat16* As_h = smem;                       // ST*AS_SIZE
    __nv_bfloat16* As_l = As_h + ST * AS_SIZE;
    __nv_bfloat16* Bs_h = As_l + ST * AS_SIZE;
    __nv_bfloat16* Bs_l = Bs_h + ST * BS_SIZE;

    const int tid  = threadIdx.x;
    const int lane = tid & 31;
    const int warp = tid >> 5;
    const int wm   = warp >> 2;   // 0..1 : 64-row slab
    const int wn   = warp & 3;    // 0..3 : 32-col slab

    const int m0 = blockIdx.y * BM;
    const int n0 = blockIdx.x * BN;

    const int jseg = n0 / seg;
    const __nv_bfloat16* Bbh = Bh + (long)jseg * segstride + (n0 - jseg * seg);
    const __nv_bfloat16* Bbl = Bl + (long)jseg * segstride + (n0 - jseg * seg);

    // per-thread staging coordinates (2 chunks of 16B per operand tensor)
    const int c0 = tid, c1 = tid + 256;
    const int ar0 = c0 >> 2, aq0 = (c0 & 3) << 3;
    const int ar1 = c1 >> 2, aq1 = (c1 & 3) << 3;
    const int br0 = c0 >> 4, bq0 = (c0 & 15) << 3;
    const int br1 = c1 >> 4, bq1 = (c1 & 15) << 3;

#define ISSUE(s, k0) do {                                                              \
    uint32_t d;                                                                        \
    d = (uint32_t)__cvta_generic_to_shared(As_h + (s)*AS_SIZE + ar0*ASTR + aq0);       \
    cpasync16(d, Ah + (long)(m0 + ar0) * lda + (k0) + aq0);                            \
    d = (uint32_t)__cvta_generic_to_shared(As_h + (s)*AS_SIZE + ar1*ASTR + aq1);       \
    cpasync16(d, Ah + (long)(m0 + ar1) * lda + (k0) + aq1);                            \
    d = (uint32_t)__cvta_generic_to_shared(As_l + (s)*AS_SIZE + ar0*ASTR + aq0);       \
    cpasync16(d, Al + (long)(m0 + ar0) * lda + (k0) + aq0);                            \
    d = (uint32_t)__cvta_generic_to_shared(As_l + (s)*AS_SIZE + ar1*ASTR + aq1);       \
    cpasync16(d, Al + (long)(m0 + ar1) * lda + (k0) + aq1);                            \
    d = (uint32_t)__cvta_generic_to_shared(Bs_h + (s)*BS_SIZE + br0*BSTR + bq0);       \
    cpasync16(d, Bbh + (long)((k0) + br0) * ldb + bq0);                                \
    d = (uint32_t)__cvta_generic_to_shared(Bs_h + (s)*BS_SIZE + br1*BSTR + bq1);       \
    cpasync16(d, Bbh + (long)((k0) + br1) * ldb + bq1);                                \
    d = (uint32_t)__cvta_generic_to_shared(Bs_l + (s)*BS_SIZE + br0*BSTR + bq0);       \
    cpasync16(d, Bbl + (long)((k0) + br0) * ldb + bq0);                                \
    d = (uint32_t)__cvta_generic_to_shared(Bs_l + (s)*BS_SIZE + br1*BSTR + bq1);       \
    cpasync16(d, Bbl + (long)((k0) + br1) * ldb + bq1);                                \
} while (0)

    float acc[4][4][4];
#pragma unroll
    for (int i = 0; i < 4; i++)
#pragma unroll
        for (int j = 0; j < 4; j++)
#pragma unroll
            for (int k = 0; k < 4; k++) acc[i][j][k] = 0.f;

    const int KT = K >> 5;

    // prologue: fill ST-1 stages
#pragma unroll
    for (int s = 0; s < ST - 1; s++) {
        ISSUE(s, s << 5);
        cp_commit();
    }

    for (int kt = 0; kt < KT; kt++) {
        cp_wait2();
        __syncthreads();
        const int stg = kt & (ST - 1);

#pragma unroll
        for (int ks = 0; ks < 2; ks++) {
            uint32_t ah[4][4], al[4][4], bh[4][2], bl[4][2];
            const int arow = wm * 64 + (lane & 15);
            const int acol = ks * 16 + ((lane >> 4) << 3);
#pragma unroll
            for (int mt = 0; mt < 4; mt++) {
                int idx = stg * AS_SIZE + (arow + mt * 16) * ASTR + acol;
                ldsm_x4(ah[mt], (uint32_t)__cvta_generic_to_shared(As_h + idx));
                ldsm_x4(al[mt], (uint32_t)__cvta_generic_to_shared(As_l + idx));
            }
            const int brow  = ks * 16 + (lane & 15);
            const int bcolb = wn * 32 + ((lane >> 4) << 3);
#pragma unroll
            for (int nt2 = 0; nt2 < 2; nt2++) {
                int idx = stg * BS_SIZE + brow * BSTR + bcolb + nt2 * 16;
                uint32_t r[4];
                ldsm_x4_t(r, (uint32_t)__cvta_generic_to_shared(Bs_h + idx));
                bh[nt2 * 2][0] = r[0]; bh[nt2 * 2][1] = r[1];
                bh[nt2 * 2 + 1][0] = r[2]; bh[nt2 * 2 + 1][1] = r[3];
                ldsm_x4_t(r, (uint32_t)__cvta_generic_to_shared(Bs_l + idx));
                bl[nt2 * 2][0] = r[0]; bl[nt2 * 2][1] = r[1];
                bl[nt2 * 2 + 1][0] = r[2]; bl[nt2 * 2 + 1][1] = r[3];
            }
#pragma unroll
            for (int mt = 0; mt < 4; mt++)
#pragma unroll
                for (int nt = 0; nt < 4; nt++) {
                    mma16816(acc[mt][nt], ah[mt], bh[nt]);   // hi*hi
                    mma16816(acc[mt][nt], ah[mt], bl[nt]);   // hi*lo
                    mma16816(acc[mt][nt], al[mt], bh[nt]);   // lo*hi
                }
        }

        const int kn = kt + ST - 1;
        if (kn < KT) {
            // writes stage (kt-1)%ST: fully consumed by all threads before the
            // __syncthreads we passed at the top of this iteration.
            ISSUE(kn & (ST - 1), kn << 5);
        }
        cp_commit();
    }
#undef ISSUE

    // ---- epilogue ----
#pragma unroll
    for (int mt = 0; mt < 4; mt++) {
        const int r0 = m0 + wm * 64 + mt * 16 + (lane >> 2);
#pragma unroll
        for (int nt = 0; nt < 4; nt++) {
            const int gc = n0 + wn * 32 + nt * 8 + ((lane & 3) << 1);
            float2 v0 = make_float2(acc[mt][nt][0], acc[mt][nt][1]);
            float2 v1 = make_float2(acc[mt][nt][2], acc[mt][nt][3]);
            if (bias) {
                float b0 = bias[gc], b1v = bias[gc + 1];
                v0.x += b0; v0.y += b1v; v1.x += b0; v1.y += b1v;
            }
            if (outF) {
                *reinterpret_cast<float2*>(outF + (long)r0 * ldF + gc) = v0;
                *reinterpret_cast<float2*>(outF + (long)(r0 + 8) * ldF + gc) = v1;
            } else {
                __nv_bfloat16 *ph, *pl;
                int col;
                if (gc < split) { ph = o0h; pl = o0l; col = gc;          }
                else            { ph = o1h; pl = o1l; col = gc - split;  }
                const int ld = (gc < split) ? ld0 : ld1;
                uint32_t h0, l0, h1, l1;
                split2(v0.x, v0.y, h0, l0);
                split2(v1.x, v1.y, h1, l1);
                *reinterpret_cast<uint32_t*>(ph + (long)r0 * ld + col)       = h0;
                *reinterpret_cast<uint32_t*>(pl + (long)r0 * ld + col)       = l0;
                *reinterpret_cast<uint32_t*>(ph + (long)(r0 + 8) * ld + col) = h1;
                *reinterpret_cast<uint32_t*>(pl + (long)(r0 + 8) * ld + col) = l1;
            }
        }
    }
}

// ---------------- batchnorm (training-mode stats) on split h ----------------
__global__ void bn_stats(const __nv_bfloat16* __restrict__ hh,
                         const __nv_bfloat16* __restrict__ hl,
                         const float* __restrict__ gamma,
                         const float* __restrict__ beta,
                         float* __restrict__ sc, float* __restrict__ sh)
{
    __shared__ float ss[16][32], sq[16][32];
    const int c   = threadIdx.x & 31;
    const int col = blockIdx.x * 32 + c;
    const int rg  = threadIdx.x >> 5;
    float s = 0.f, s2 = 0.f;
    for (int r = rg; r < NN; r += 16) {
        long i = (long)r * H3 + col;
        float v = __bfloat162float(hh[i]) + __bfloat162float(hl[i]);
        s += v; s2 += v * v;
    }
    ss[rg][c] = s; sq[rg][c] = s2;
    __syncthreads();
    if (rg == 0) {
#pragma unroll
        for (int k = 1; k < 16; k++) { s += ss[k][c]; s2 += sq[k][c]; }
        const float mean = s * (1.f / NN);
        const float var  = s2 * (1.f / NN) - mean * mean;
        const float scale = gamma[col] * rsqrtf(var + 1e-5f);
        sc[col] = scale;
        sh[col] = beta[col] - mean * scale;
    }
}

// h = relu(h*sc + sh), in-place on split rep, 4 elems/thread
__global__ void bn_apply_relu(__nv_bfloat16* __restrict__ hh,
                              __nv_bfloat16* __restrict__ hl,
                              const float* __restrict__ sc,
                              const float* __restrict__ sh)
{
    const long i = ((long)blockIdx.x * blockDim.x + threadIdx.x) * 4;
    uint2 uh = *reinterpret_cast<uint2*>(hh + i);
    uint2 ul = *reinterpret_cast<uint2*>(hl + i);
    float2 a01 = __bfloat1622float2(*reinterpret_cast<__nv_bfloat162*>(&uh.x));
    float2 a23 = __bfloat1622float2(*reinterpret_cast<__nv_bfloat162*>(&uh.y));
    float2 b01 = __bfloat1622float2(*reinterpret_cast<__nv_bfloat162*>(&ul.x));
    float2 b23 = __bfloat1622float2(*reinterpret_cast<__nv_bfloat162*>(&ul.y));
    const int c = (int)(i % H3);
    float y0 = fmaxf(0.f, (a01.x + b01.x) * sc[c]     + sh[c]);
    float y1 = fmaxf(0.f, (a01.y + b01.y) * sc[c + 1] + sh[c + 1]);
    float y2 = fmaxf(0.f, (a23.x + b23.x) * sc[c + 2] + sh[c + 2]);
    float y3 = fmaxf(0.f, (a23.y + b23.y) * sc[c + 3] + sh[c + 3]);
    uint32_t h0, l0, h1, l1;
    split2(y0, y1, h0, l0);
    split2(y2, y3, h1, l1);
    *reinterpret_cast<uint2*>(hh + i) = make_uint2(h0, h1);
    *reinterpret_cast<uint2*>(hl + i) = make_uint2(l0, l1);
}

// ---------------- launcher ----------------
struct Ptrs {
    __nv_bfloat16 *adjh, *adjl, *xh, *xl, *w1h, *w1l, *w2h, *w2l, *wfh, *wfl;
    __nv_bfloat16 *hh, *hl, *zth, *ztl, *u1h, *u1l, *gh, *gl, *z2h, *z2l, *u2h, *u2l;
    float *sc, *sh;
};
static void get_ptrs(Ptrs& p) {
    cudaGetSymbolAddress((void**)&p.adjh, g_adj_h); cudaGetSymbolAddress((void**)&p.adjl, g_adj_l);
    cudaGetSymbolAddress((void**)&p.xh, g_x_h);     cudaGetSymbolAddress((void**)&p.xl, g_x_l);
    cudaGetSymbolAddress((void**)&p.w1h, g_w1_h);   cudaGetSymbolAddress((void**)&p.w1l, g_w1_l);
    cudaGetSymbolAddress((void**)&p.w2h, g_w2_h);   cudaGetSymbolAddress((void**)&p.w2l, g_w2_l);
    cudaGetSymbolAddress((void**)&p.wfh, g_wf_h);   cudaGetSymbolAddress((void**)&p.wfl, g_wf_l);
    cudaGetSymbolAddress((void**)&p.hh, g_hh);      cudaGetSymbolAddress((void**)&p.hl, g_hl);
    cudaGetSymbolAddress((void**)&p.zth, g_zth);    cudaGetSymbolAddress((void**)&p.ztl, g_ztl);
    cudaGetSymbolAddress((void**)&p.u1h, g_u1h);    cudaGetSymbolAddress((void**)&p.u1l, g_u1l);
    cudaGetSymbolAddress((void**)&p.gh, g_gh);      cudaGetSymbolAddress((void**)&p.gl, g_gl);
    cudaGetSymbolAddress((void**)&p.z2h, g_z2h);    cudaGetSymbolAddress((void**)&p.z2l, g_z2l);
    cudaGetSymbolAddress((void**)&p.u2h, g_u2h);    cudaGetSymbolAddress((void**)&p.u2l, g_u2l);
    cudaGetSymbolAddress((void**)&p.sc, g_sc);      cudaGetSymbolAddress((void**)&p.sh, g_sh);
}

static inline void run_conv(const float* in, __nv_bfloat16* oh, __nv_bfloat16* ol, long n) {
    convert_split<<<(int)(n / 1024), 256>>>(in, oh, ol, n);
}

static inline void run_gemm(const __nv_bfloat16* Ah, const __nv_bfloat16* Al, int lda,
                            const __nv_bfloat16* Bh, const __nv_bfloat16* Bl,
                            int ldb, int seg, long segstride,
                            const float* bias,
                            __nv_bfloat16* o0h, __nv_bfloat16* o0l, int ld0, int split,
                            __nv_bfloat16* o1h, __nv_bfloat16* o1l, int ld1,
                            float* outF, int ldF,
                            int M, int N, int K)
{
    dim3 grid(N / BN, M / BM);
    gemm_bf16split<<<grid, 256, SMEM_BYTES>>>(Ah, Al, lda, Bh, Bl, ldb, seg, segstride,
                                              bias, o0h, o0l, ld0, split, o1h, o1l, ld1,
                                              outF, ldF, K);
}

extern "C" void kernel_launch(void* const* d_in, const int* in_sizes, int n_in,
                              void* d_out, int out_size)
{
    const float* x     = (const float*)d_in[0];
    const float* adj   = (const float*)d_in[1];
    const float* W1    = (const float*)d_in[2];
    const float* b1    = (const float*)d_in[3];
    const float* W2    = (const float*)d_in[4];
    const float* b2    = (const float*)d_in[5];
    const float* gamma = (const float*)d_in[6];
    const float* beta  = (const float*)d_in[7];
    const float* Wf    = (const float*)d_in[8];
    const float* bf    = (const float*)d_in[9];
    float* out = (float*)d_out;

    Ptrs p; get_ptrs(p);
    cudaFuncSetAttribute(gemm_bf16split,
                         cudaFuncAttributeMaxDynamicSharedMemorySize, SMEM_BYTES);

    // ---- pre-split all external operands ----
    run_conv(adj, p.adjh, p.adjl, (long)NN * NN);
    run_conv(x,   p.xh,   p.xl,   (long)NN * INF);
    run_conv(W1,  p.w1h,  p.w1l,  3L * INF * HID);
    run_conv(W2,  p.w2h,  p.w2l,  3L * H3 * OUTF);
    run_conv(Wf,  p.wfh,  p.wfl,  (long)O3 * OUTF);

    // ---- layer 1 ----
    // G1: x @ [W1_0|W1_1|W1_2] + b1 -> hop0 into h[:,0:512], hops1/2 into ZT
    run_gemm(p.xh, p.xl, INF, p.w1h, p.w1l, HID, HID, (long)INF * HID, b1,
             p.hh, p.hl, H3, HID, p.zth, p.ztl, 1024, nullptr, 0, NN, H3, INF);
    // G2: adj @ ZT -> hop1 into h[:,512:1024], hop2-intermediate into U1
    run_gemm(p.adjh, p.adjl, NN, p.zth, p.ztl, 1024, 1024, 0, nullptr,
             p.hh + HID, p.hl + HID, H3, HID, p.u1h, p.u1l, HID, nullptr, 0, NN, 1024, NN);
    // G3: adj @ U1 -> hop2 into h[:,1024:1536]
    run_gemm(p.adjh, p.adjl, NN, p.u1h, p.u1l, HID, HID, 0, nullptr,
             p.hh + 2 * HID, p.hl + 2 * HID, H3, HID, nullptr, nullptr, 0, nullptr, 0,
             NN, HID, NN);

    // ---- batchnorm + relu (on split rep) ----
    bn_stats<<<H3 / 32, 512>>>(p.hh, p.hl, gamma, beta, p.sc, p.sh);
    bn_apply_relu<<<(NN * H3 / 4) / 256, 256>>>(p.hh, p.hl, p.sc, p.sh);

    // ---- layer 2 ----
    // G4: h @ [W2_0|W2_1|W2_2] + b2 -> hop0 into g[:,0:256], hops1/2 into Z2
    run_gemm(p.hh, p.hl, H3, p.w2h, p.w2l, OUTF, OUTF, (long)H3 * OUTF, b2,
             p.gh, p.gl, O3, OUTF, p.z2h, p.z2l, 512, nullptr, 0, NN, O3, H3);
    // G5: adj @ Z2 -> hop1 into g[:,256:512], hop2-intermediate into U2
    run_gemm(p.adjh, p.adjl, NN, p.z2h, p.z2l, 512, 512, 0, nullptr,
             p.gh + OUTF, p.gl + OUTF, O3, OUTF, p.u2h, p.u2l, OUTF, nullptr, 0,
             NN, 512, NN);
    // G6: adj @ U2 -> hop2 into g[:,512:768]
    run_gemm(p.adjh, p.adjl, NN, p.u2h, p.u2l, OUTF, OUTF, 0, nullptr,
             p.gh + 2 * OUTF, p.gl + 2 * OUTF, O3, OUTF, nullptr, nullptr, 0, nullptr, 0,
             NN, OUTF, NN);

    // ---- final linear: g @ Wf + bf -> fp32 out ----
    run_gemm(p.gh, p.gl, O3, p.wfh, p.wfl, OUTF, OUTF, 0, bf,
             nullptr, nullptr, 0, OUTF, nullptr, nullptr, 0, out, OUTF, NN, OUTF, O3);
}